// round 15
// baseline (speedup 1.0000x reference)
#include <cuda_runtime.h>
#include <cuda_bf16.h>
#include <math.h>
#include <stdint.h>

#define Bb 2
#define Ll 2048
#define DMM 512
#define Hh 8
#define Dd 64
#define NUMK 40
#define NUMQ 40
#define LN_EPS 1e-5f

// ---------------- scratch (static device globals; no allocs allowed) ----------------
__device__ __align__(256) float g_qp[Bb*Ll*DMM];
__device__ __align__(256) float g_kp[Bb*Ll*DMM];
__device__ __align__(256) float g_vp[Bb*Ll*DMM];
__device__ __align__(256) float g_measure[Bb*Hh*Ll];
__device__ __align__(256) float g_vpart[Bb*128*DMM];
__device__ __align__(256) float g_vmean[Bb*DMM];
__device__ __align__(256) int   g_qidx[Bb*Hh*NUMQ];
__device__ __align__(256) int   g_slot[Bb*Hh*Ll];
__device__ __align__(256) float g_outsel[Bb*Hh*NUMQ*Dd];
// W transposed + bf16 hi/lo split: [which][N][K]
__device__ __align__(256) __nv_bfloat16 g_Wth[3*DMM*DMM];
__device__ __align__(256) __nv_bfloat16 g_Wtl[3*DMM*DMM];

// ============================ helpers ============================
__device__ __forceinline__ uint32_t smem_u32(const void* p) {
    uint32_t a;
    asm("{ .reg .u64 t; cvta.to.shared.u64 t, %1; cvt.u32.u64 %0, t; }" : "=r"(a) : "l"(p));
    return a;
}
#define SWZ128(off) ((off) ^ (((off) >> 3) & 0x70))

#define STS128(addr, a, b, c, d) \
    asm volatile("st.shared.v4.b32 [%0], {%1, %2, %3, %4};" \
                 :: "r"(addr), "r"(a), "r"(b), "r"(c), "r"(d) : "memory")

__device__ __forceinline__ void ldsm4(uint32_t& r0, uint32_t& r1, uint32_t& r2, uint32_t& r3,
                                      uint32_t addr) {
    asm volatile("ldmatrix.sync.aligned.m8n8.x4.shared.b16 {%0,%1,%2,%3}, [%4];"
                 : "=r"(r0), "=r"(r1), "=r"(r2), "=r"(r3) : "r"(addr));
}
__device__ __forceinline__ void mma16816(float* c, const uint32_t* a, uint32_t b0, uint32_t b1) {
    asm volatile(
        "mma.sync.aligned.m16n8k16.row.col.f32.bf16.bf16.f32 "
        "{%0,%1,%2,%3}, {%4,%5,%6,%7}, {%8,%9}, {%0,%1,%2,%3};"
        : "+f"(c[0]), "+f"(c[1]), "+f"(c[2]), "+f"(c[3])
        : "r"(a[0]), "r"(a[1]), "r"(a[2]), "r"(a[3]), "r"(b0), "r"(b1));
}

__device__ __forceinline__ void split2(float a, float b, uint32_t& h, uint32_t& l) {
    __nv_bfloat16 ha = __float2bfloat16(a), hb = __float2bfloat16(b);
    __nv_bfloat16 la = __float2bfloat16(a - __bfloat162float(ha));
    __nv_bfloat16 lb = __float2bfloat16(b - __bfloat162float(hb));
    __nv_bfloat162 hh(ha, hb), ll(la, lb);
    h = *reinterpret_cast<uint32_t*>(&hh);
    l = *reinterpret_cast<uint32_t*>(&ll);
}

__device__ __forceinline__ bool kbetter(float av, int ai, float bv, int bi) {
    return av > bv || (av == bv && ai < bi);
}

// ---------------- W transpose + bf16 split: Wt[n][k] = W[k][n] ----------------
__global__ void wsplit_t_kernel(const float* __restrict__ Wq,
                                const float* __restrict__ Wk,
                                const float* __restrict__ Wv)
{
    int which = blockIdx.z;
    const float* W = (which == 0) ? Wq : (which == 1) ? Wk : Wv;
    __nv_bfloat16* Th = g_Wth + (size_t)which * DMM * DMM;
    __nv_bfloat16* Tl = g_Wtl + (size_t)which * DMM * DMM;
    __shared__ float tile[32][33];
    int n0 = blockIdx.x * 32, k0 = blockIdx.y * 32;
    int x = threadIdx.x, y = threadIdx.y;   // 32 x 8
#pragma unroll
    for (int yy = 0; yy < 32; yy += 8)
        tile[y + yy][x] = W[(size_t)(k0 + y + yy) * DMM + n0 + x];
    __syncthreads();
#pragma unroll
    for (int yy = 0; yy < 32; yy += 8) {
        int n = n0 + y + yy;
        float f = tile[x][y + yy];           // = W[k0+x][n]
        __nv_bfloat16 h = __float2bfloat16(f);
        Th[(size_t)n * DMM + k0 + x] = h;
        Tl[(size_t)n * DMM + k0 + x] = __float2bfloat16(f - __bfloat162float(h));
    }
}

// ---------------- HMMA GEMM: 512 threads, 16 warps of 32x32 ----------------
#define OFF_AH 0
#define OFF_AL 16384
#define OFF_BH 32768
#define OFF_BL 49152
#define GEMM_SMEM 66560

__global__ void __launch_bounds__(512, 1)
gemm_tc_kernel(const float* __restrict__ qin, const float* __restrict__ kin,
               const float* __restrict__ vin,
               const float* __restrict__ bq, const float* __restrict__ bk,
               const float* __restrict__ bv, int zbase)
{
    extern __shared__ char dsm[];

    int which = blockIdx.z + zbase;
    const float* A    = (which == 0) ? qin : (which == 1) ? kin : vin;
    const float* bias = (which == 0) ? bq  : (which == 1) ? bk  : bv;
    float* C          = (which == 0) ? g_qp : (which == 1) ? g_kp : g_vp;
    const __nv_bfloat16* Bh = g_Wth + (size_t)which * DMM * DMM;
    const __nv_bfloat16* Bl = g_Wtl + (size_t)which * DMM * DMM;

    int tid = threadIdx.x, wid = tid >> 5, lane = tid & 31;
    int m0 = blockIdx.y * 128, n0 = blockIdx.x * 128;
    int wm = wid & 3, wn = wid >> 2;

    uint32_t sb = (smem_u32(dsm) + 1023u) & ~1023u;

    uint32_t soff[2];
    int rr[2], cc[2];
#pragma unroll
    for (int jj = 0; jj < 2; jj++) {
        int i = tid + 512 * jj;
        rr[jj] = i >> 3;
        cc[jj] = i & 7;
        soff[jj] = SWZ128((uint32_t)(rr[jj] * 128 + cc[jj] * 16));
    }

    uint32_t a_off[2], b_off[2];
#pragma unroll
    for (int mt = 0; mt < 2; mt++)
        a_off[mt] = (uint32_t)((wm * 32 + mt * 16 + (lane & 15)) * 128);
#pragma unroll
    for (int bt = 0; bt < 2; bt++)
        b_off[bt] = (uint32_t)((wn * 32 + bt * 16 + (lane & 15)) * 128);
    int lhalf = lane >> 4;

    float acc[2][4][4];
#pragma unroll
    for (int i = 0; i < 2; i++)
#pragma unroll
        for (int j = 0; j < 4; j++)
#pragma unroll
            for (int c = 0; c < 4; c++) acc[i][j][c] = 0.f;

    float4 fa[4];
    uint4 vbh[2], vbl[2];

#pragma unroll
    for (int jj = 0; jj < 2; jj++) {
        const float* pa = A + (size_t)(m0 + rr[jj]) * DMM + cc[jj] * 8;
        fa[2*jj]   = *(const float4*)pa;
        fa[2*jj+1] = *(const float4*)(pa + 4);
        vbh[jj] = *(const uint4*)(Bh + (size_t)(n0 + rr[jj]) * DMM + cc[jj] * 8);
        vbl[jj] = *(const uint4*)(Bl + (size_t)(n0 + rr[jj]) * DMM + cc[jj] * 8);
    }

    for (int kt = 0; kt < 8; kt++) {
#pragma unroll
        for (int jj = 0; jj < 2; jj++) {
            uint32_t h0,h1,h2,h3,l0,l1,l2,l3;
            split2(fa[2*jj].x,   fa[2*jj].y,   h0, l0);
            split2(fa[2*jj].z,   fa[2*jj].w,   h1, l1);
            split2(fa[2*jj+1].x, fa[2*jj+1].y, h2, l2);
            split2(fa[2*jj+1].z, fa[2*jj+1].w, h3, l3);
            STS128(sb + OFF_AH + soff[jj], h0, h1, h2, h3);
            STS128(sb + OFF_AL + soff[jj], l0, l1, l2, l3);
            STS128(sb + OFF_BH + soff[jj], vbh[jj].x, vbh[jj].y, vbh[jj].z, vbh[jj].w);
            STS128(sb + OFF_BL + soff[jj], vbl[jj].x, vbl[jj].y, vbl[jj].z, vbl[jj].w);
        }
        __syncthreads();

        if (kt < 7) {
            int kb = (kt + 1) * 64;
#pragma unroll
            for (int jj = 0; jj < 2; jj++) {
                const float* pa = A + (size_t)(m0 + rr[jj]) * DMM + kb + cc[jj] * 8;
                fa[2*jj]   = *(const float4*)pa;
                fa[2*jj+1] = *(const float4*)(pa + 4);
                vbh[jj] = *(const uint4*)(Bh + (size_t)(n0 + rr[jj]) * DMM + kb + cc[jj] * 8);
                vbl[jj] = *(const uint4*)(Bl + (size_t)(n0 + rr[jj]) * DMM + kb + cc[jj] * 8);
            }
        }

#pragma unroll
        for (int ks = 0; ks < 4; ks++) {
            uint32_t chunk = (uint32_t)((2*ks + lhalf) * 16);
            uint32_t ah[2][4], al[2][4];
#pragma unroll
            for (int mt = 0; mt < 2; mt++) {
                uint32_t sw = SWZ128(a_off[mt] + chunk);
                ldsm4(ah[mt][0], ah[mt][1], ah[mt][2], ah[mt][3], sb + OFF_AH + sw);
                ldsm4(al[mt][0], al[mt][1], al[mt][2], al[mt][3], sb + OFF_AL + sw);
            }
            uint32_t bh[2][4], bl[2][4];
#pragma unroll
            for (int bt = 0; bt < 2; bt++) {
                uint32_t sw = SWZ128(b_off[bt] + chunk);
                ldsm4(bh[bt][0], bh[bt][1], bh[bt][2], bh[bt][3], sb + OFF_BH + sw);
                ldsm4(bl[bt][0], bl[bt][1], bl[bt][2], bl[bt][3], sb + OFF_BL + sw);
            }
#pragma unroll
            for (int mt = 0; mt < 2; mt++)
#pragma unroll
                for (int nt = 0; nt < 4; nt++) {
                    int bt = nt >> 1, hi = nt & 1;
                    mma16816(acc[mt][nt], ah[mt], bh[bt][hi], bh[bt][hi+2]);
                }
#pragma unroll
            for (int mt = 0; mt < 2; mt++)
#pragma unroll
                for (int nt = 0; nt < 4; nt++) {
                    int bt = nt >> 1, hi = nt & 1;
                    mma16816(acc[mt][nt], ah[mt], bl[bt][hi], bl[bt][hi+2]);
                }
#pragma unroll
            for (int mt = 0; mt < 2; mt++)
#pragma unroll
                for (int nt = 0; nt < 4; nt++) {
                    int bt = nt >> 1, hi = nt & 1;
                    mma16816(acc[mt][nt], al[mt], bh[bt][hi], bh[bt][hi+2]);
                }
        }
        __syncthreads();
    }

#pragma unroll
    for (int mt = 0; mt < 2; mt++) {
        int mrow = m0 + wm*32 + mt*16 + (lane >> 2);
#pragma unroll
        for (int nt = 0; nt < 4; nt++) {
            int ncol = n0 + wn*32 + nt*8 + (lane & 3)*2;
            float b0 = bias[ncol], b1 = bias[ncol + 1];
            float2 v0 = make_float2(acc[mt][nt][0] + b0, acc[mt][nt][1] + b1);
            float2 v1 = make_float2(acc[mt][nt][2] + b0, acc[mt][nt][3] + b1);
            *(float2*)(C + (size_t)mrow * DMM + ncol)       = v0;
            *(float2*)(C + (size_t)(mrow + 8) * DMM + ncol) = v1;
        }
    }
}

// ---------------- v_mean (two-stage, deterministic) ----------------
__global__ void vmean_part_kernel() {
    int blk = blockIdx.x;               // 256
    int b = blk >> 7, j = blk & 127;    // 16 rows each
    int c = threadIdx.x;                // 512
    int base = j * 16;
    const float* p = &g_vp[((size_t)b*Ll + base)*DMM + c];
    float s0 = 0.f, s1 = 0.f, s2 = 0.f, s3 = 0.f;
#pragma unroll
    for (int l = 0; l < 16; l += 4) {
        s0 += p[(size_t)(l  )*DMM];
        s1 += p[(size_t)(l+1)*DMM];
        s2 += p[(size_t)(l+2)*DMM];
        s3 += p[(size_t)(l+3)*DMM];
    }
    g_vpart[(size_t)blk*DMM + c] = (s0 + s1) + (s2 + s3);
}
__global__ void vmean_reduce_kernel() {
    int b = blockIdx.x; int c = threadIdx.x;
    const float* p = &g_vpart[(size_t)b*128*DMM + c];
    float s[16];
#pragma unroll
    for (int i = 0; i < 16; i++) s[i] = p[(size_t)i*DMM];
#pragma unroll
    for (int j = 16; j < 128; j += 16)
#pragma unroll
        for (int i = 0; i < 16; i++) s[i] += p[(size_t)(j+i)*DMM];
    float t = 0.f;
#pragma unroll
    for (int i = 0; i < 16; i++) t += s[i];
    g_vmean[b*DMM + c] = t * (1.0f / Ll);
}

// ---------------- pre + measure: 2 warps per (b,l), 20 samples each ----------------
__global__ __launch_bounds__(256) void measure_kernel(const int* __restrict__ ridx) {
    __shared__ float smx[4][2][8], ssm[4][2][8];
    int tid = threadIdx.x, warp = tid >> 5, lane = tid & 31;
    int p = warp >> 1, half = warp & 1;
    int gp = blockIdx.x * 4 + p;           // 0..4095
    int l = gp & (Ll - 1), b = gp >> 11;
    const float4* qrow = (const float4*)&g_qp[((size_t)b*Ll + l) * DMM];
    float4 q0 = qrow[lane*4+0], q1 = qrow[lane*4+1], q2 = qrow[lane*4+2], q3 = qrow[lane*4+3];
    int idx = ridx[l*NUMK + half*20 + (lane >= 20 ? lane - 20 : lane)];
    float mx = -INFINITY, sm = 0.f;
#pragma unroll 4
    for (int j = 0; j < 20; j++) {
        int ki = __shfl_sync(0xffffffffu, idx, j);
        const float4* kr = (const float4*)&g_kp[((size_t)b*Ll + ki) * DMM];
        float4 k0 = kr[lane*4+0], k1 = kr[lane*4+1], k2 = kr[lane*4+2], k3 = kr[lane*4+3];
        float pv = q0.x*k0.x + q0.y*k0.y + q0.z*k0.z + q0.w*k0.w
                 + q1.x*k1.x + q1.y*k1.y + q1.z*k1.z + q1.w*k1.w
                 + q2.x*k2.x + q2.y*k2.y + q2.z*k2.z + q2.w*k2.w
                 + q3.x*k3.x + q3.y*k3.y + q3.z*k3.z + q3.w*k3.w;
        pv += __shfl_xor_sync(0xffffffffu, pv, 1);
        pv += __shfl_xor_sync(0xffffffffu, pv, 2);
        mx = fmaxf(mx, pv);
        sm += pv;
    }
    if ((lane & 3) == 0) {
        smx[p][half][lane >> 2] = mx;
        ssm[p][half][lane >> 2] = sm;
    }
    __syncthreads();
    if (tid < 32) {
        int pp = tid >> 3, h = tid & 7;
        float m = fmaxf(smx[pp][0][h], smx[pp][1][h]);
        float s = ssm[pp][0][h] + ssm[pp][1][h];
        int gpp = blockIdx.x * 4 + pp;
        int ll = gpp & (Ll - 1), bb = gpp >> 11;
        g_measure[((size_t)bb*Hh + h)*Ll + ll] = m - s * (1.0f / Ll);
    }
}

// ---------------- exact top-40 per (b,h): top-2 per round (20 rounds) ----------------
__global__ __launch_bounds__(256) void topk_kernel() {
    int bh = blockIdx.x, t = threadIdx.x;
    int w = t >> 5, lane = t & 31;
    for (int i = t; i < Ll; i += 256) g_slot[(size_t)bh*Ll + i] = -1;
    float v[8];
    const float* src = g_measure + (size_t)bh * Ll;
#pragma unroll
    for (int m = 0; m < 8; m++) v[m] = src[t + 256*m];
    __shared__ float sv1[8], sv2[8];
    __shared__ int   si1[8], si2[8];
    __shared__ int   s_a, s_b;
    __shared__ int   qsel[NUMQ];
    for (int s = 0; s < NUMQ; s += 2) {
        // thread-local top-2 of its 8 values
        float b1v = -INFINITY, b2v = -INFINITY;
        int   b1i = 0x7fffffff, b2i = 0x7fffffff;
#pragma unroll
        for (int m = 0; m < 8; m++) {
            int i = t + 256*m;
            if (kbetter(v[m], i, b1v, b1i)) {
                b2v = b1v; b2i = b1i; b1v = v[m]; b1i = i;
            } else if (kbetter(v[m], i, b2v, b2i)) {
                b2v = v[m]; b2i = i;
            }
        }
        // warp merge of top-2 pairs
#pragma unroll
        for (int o = 16; o; o >>= 1) {
            float o1v = __shfl_xor_sync(0xffffffffu, b1v, o);
            int   o1i = __shfl_xor_sync(0xffffffffu, b1i, o);
            float o2v = __shfl_xor_sync(0xffffffffu, b2v, o);
            int   o2i = __shfl_xor_sync(0xffffffffu, b2i, o);
            if (kbetter(o1v, o1i, b1v, b1i)) {
                float n2v; int n2i;
                if (kbetter(b1v, b1i, o2v, o2i)) { n2v = b1v; n2i = b1i; }
                else                             { n2v = o2v; n2i = o2i; }
                b1v = o1v; b1i = o1i; b2v = n2v; b2i = n2i;
            } else {
                if (kbetter(o1v, o1i, b2v, b2i)) { b2v = o1v; b2i = o1i; }
            }
        }
        if (lane == 0) { sv1[w] = b1v; si1[w] = b1i; sv2[w] = b2v; si2[w] = b2i; }
        __syncthreads();
        if (t == 0) {
            float r1v = sv1[0], r2v = sv2[0];
            int   r1i = si1[0], r2i = si2[0];
#pragma unroll
            for (int ww = 1; ww < 8; ww++) {
                float o1v = sv1[ww], o2v = sv2[ww];
                int   o1i = si1[ww], o2i = si2[ww];
                if (kbetter(o1v, o1i, r1v, r1i)) {
                    float n2v; int n2i;
                    if (kbetter(r1v, r1i, o2v, o2i)) { n2v = r1v; n2i = r1i; }
                    else                             { n2v = o2v; n2i = o2i; }
                    r1v = o1v; r1i = o1i; r2v = n2v; r2i = n2i;
                } else {
                    if (kbetter(o1v, o1i, r2v, r2i)) { r2v = o1v; r2i = o1i; }
                }
            }
            g_qidx[bh*NUMQ + s]     = r1i;
            g_qidx[bh*NUMQ + s + 1] = r2i;
            qsel[s] = r1i; qsel[s + 1] = r2i;
            s_a = r1i; s_b = r2i;
        }
        __syncthreads();
        int ia = s_a, ib = s_b;
        if ((ia & 255) == t) v[ia >> 8] = -INFINITY;
        if ((ib & 255) == t) v[ib >> 8] = -INFINITY;
    }
    if (t < NUMQ) g_slot[(size_t)bh * Ll + qsel[t]] = t;
}

// ---------------- attention: 512 threads, block per (b,h,group-of-4-q) ----------------
__global__ __launch_bounds__(512) void attn_kernel(float* __restrict__ out_attn) {
    int blk = blockIdx.x;
    int g = blk % 10;
    int h = (blk / 10) % Hh;
    int b = blk / (10 * Hh);
    __shared__ float qs[4][Dd];
    __shared__ float sc[4][Ll];
    __shared__ float red[16];
    __shared__ float pvs[8][4][Dd];
    __shared__ int qix[4];
    int tid = threadIdx.x;
    int lane = tid & 31, w = tid >> 5;      // 16 warps
    if (tid < 4) qix[tid] = g_qidx[(b*Hh + h)*NUMQ + g*4 + tid];
    __syncthreads();
    if (tid < 256) {
        int qq = tid >> 6, d = tid & 63;
        qs[qq][d] = g_qp[((size_t)b*Ll + qix[qq])*DMM + h*Dd + d];
    }
    __syncthreads();
    const float scale = 0.125f;

    int quarter = lane & 3, keyoff = lane >> 2;
    float4 qr[4][4];
#pragma unroll
    for (int q = 0; q < 4; q++)
#pragma unroll
        for (int c = 0; c < 4; c++)
            qr[q][c] = *(float4*)&qs[q][quarter*16 + c*4];

    for (int pass = 0; pass < 16; pass++) {
        int j = w*128 + pass*8 + keyoff;
        const float4* kr = (const float4*)&g_kp[((size_t)b*Ll + j)*DMM + h*Dd + quarter*16];
        float4 k0 = kr[0], k1 = kr[1], k2 = kr[2], k3 = kr[3];
        float p[4];
#pragma unroll
        for (int q = 0; q < 4; q++) {
            p[q] = qr[q][0].x*k0.x + qr[q][0].y*k0.y + qr[q][0].z*k0.z + qr[q][0].w*k0.w
                 + qr[q][1].x*k1.x + qr[q][1].y*k1.y + qr[q][1].z*k1.z + qr[q][1].w*k1.w
                 + qr[q][2].x*k2.x + qr[q][2].y*k2.y + qr[q][2].z*k2.z + qr[q][2].w*k2.w
                 + qr[q][3].x*k3.x + qr[q][3].y*k3.y + qr[q][3].z*k3.z + qr[q][3].w*k3.w;
            p[q] += __shfl_xor_sync(0xffffffffu, p[q], 1);
            p[q] += __shfl_xor_sync(0xffffffffu, p[q], 2);
        }
        if (quarter == 0) {
            sc[0][j] = p[0] * scale; sc[1][j] = p[1] * scale;
            sc[2][j] = p[2] * scale; sc[3][j] = p[3] * scale;
        }
    }
    __syncthreads();
#pragma unroll
    for (int q = 0; q < 4; q++) {
        float m = -INFINITY;
        for (int j = tid; j < Ll; j += 512) m = fmaxf(m, sc[q][j]);
#pragma unroll
        for (int o = 16; o; o >>= 1) m = fmaxf(m, __shfl_xor_sync(0xffffffffu, m, o));
        if (lane == 0) red[w] = m;
        __syncthreads();
        m = red[0];
#pragma unroll
        for (int i = 1; i < 16; i++) m = fmaxf(m, red[i]);
        __syncthreads();
        float s = 0.f;
        for (int j = tid; j < Ll; j += 512) { float e = expf(sc[q][j] - m); sc[q][j] = e; s += e; }
#pragma unroll
        for (int o = 16; o; o >>= 1) s += __shfl_xor_sync(0xffffffffu, s, o);
        if (lane == 0) red[w] = s;
        __syncthreads();
        float tot = red[0];
#pragma unroll
        for (int i = 1; i < 16; i++) tot += red[i];
        float inv = 1.0f / tot;
        size_t aoff = ((size_t)(b*Hh + h)*NUMQ + g*4 + q) * Ll;
        for (int j = tid; j < Ll; j += 512) {
            float p = sc[q][j] * inv;
            sc[q][j] = p;
            out_attn[aoff + j] = p;
        }
        __syncthreads();
    }
    int d = tid & 63, part = tid >> 6;
    float a0 = 0.f, a1 = 0.f, a2 = 0.f, a3 = 0.f;
    int j0 = part * 256;
    const float* vbase = &g_vp[((size_t)b*Ll + j0)*DMM + h*Dd + d];
    for (int jb = 0; jb < 256; jb++) {
        float vv = vbase[(size_t)jb*DMM];
        int j = j0 + jb;
        a0 += sc[0][j]*vv; a1 += sc[1][j]*vv; a2 += sc[2][j]*vv; a3 += sc[3][j]*vv;
    }
    pvs[part][0][d] = a0; pvs[part][1][d] = a1;
    pvs[part][2][d] = a2; pvs[part][3][d] = a3;
    __syncthreads();
    if (part == 0) {
#pragma unroll
        for (int q = 0; q < 4; q++) {
            float r = 0.f;
#pragma unroll
            for (int pp = 0; pp < 8; pp++) r += pvs[pp][q][d];
            g_outsel[((size_t)((b*Hh + h)*NUMQ) + g*4 + q)*Dd + d] = r;
        }
    }
}

// ---------------- residual + layernorm (vmean/outsel compose) ----------------
__global__ __launch_bounds__(256) void ln_kernel(const float* __restrict__ qin,
                                                 const float* __restrict__ gamma,
                                                 const float* __restrict__ beta,
                                                 float* __restrict__ out)
{
    int row = blockIdx.x;            // Bb*Ll
    int b = row >> 11, l = row & (Ll - 1);
    int tid = threadIdx.x;
    __shared__ float sm[8], sm2[8];
    __shared__ int slots[8];
    if (tid < 8) slots[tid] = g_slot[(size_t)(b*Hh + tid)*Ll + l];
    __syncthreads();
    const float* qr = qin + (size_t)row * DMM;
    int c0 = tid, c1 = tid + 256;
    int h0 = c0 >> 6, h1 = c1 >> 6;
    int s0i = slots[h0], s1i = slots[h1];
    float ctx0 = (s0i >= 0)
        ? g_outsel[((size_t)((b*Hh + h0)*NUMQ) + s0i)*Dd + (c0 & 63)]
        : g_vmean[b*DMM + c0];
    float ctx1 = (s1i >= 0)
        ? g_outsel[((size_t)((b*Hh + h1)*NUMQ) + s1i)*Dd + (c1 & 63)]
        : g_vmean[b*DMM + c1];
    float v0 = ctx0 + qr[c0];
    float v1 = ctx1 + qr[c1];
    int lane = tid & 31, w = tid >> 5;
    float s = v0 + v1;
#pragma unroll
    for (int o = 16; o; o >>= 1) s += __shfl_xor_sync(0xffffffffu, s, o);
    if (lane == 0) sm[w] = s;
    __syncthreads();
    float mean = (sm[0]+sm[1]+sm[2]+sm[3]+sm[4]+sm[5]+sm[6]+sm[7]) * (1.0f / DMM);
    float d0 = v0 - mean, d1 = v1 - mean;
    float s2 = d0*d0 + d1*d1;
#pragma unroll
    for (int o = 16; o; o >>= 1) s2 += __shfl_xor_sync(0xffffffffu, s2, o);
    if (lane == 0) sm2[w] = s2;
    __syncthreads();
    float var = (sm2[0]+sm2[1]+sm2[2]+sm2[3]+sm2[4]+sm2[5]+sm2[6]+sm2[7]) * (1.0f / DMM);
    float invstd = rsqrtf(var + LN_EPS);
    out[(size_t)row*DMM + c0] = d0 * invstd * gamma[c0] + beta[c0];
    out[(size_t)row*DMM + c1] = d1 * invstd * gamma[c1] + beta[c1];
}

// ---------------- launch ----------------
extern "C" void kernel_launch(void* const* d_in, const int* in_sizes, int n_in,
                              void* d_out, int out_size)
{
    const float* q     = (const float*)d_in[0];
    const float* k     = (const float*)d_in[1];
    const float* v     = (const float*)d_in[2];
    const float* Wq    = (const float*)d_in[3];
    const float* bq    = (const float*)d_in[4];
    const float* Wk    = (const float*)d_in[5];
    const float* bk    = (const float*)d_in[6];
    const float* Wv    = (const float*)d_in[7];
    const float* bv    = (const float*)d_in[8];
    const float* gamma = (const float*)d_in[9];
    const float* beta  = (const float*)d_in[10];
    const int*   ridx  = (const int*)d_in[11];
    float* out      = (float*)d_out;
    float* out_attn = out + (size_t)Bb * Ll * DMM;

    static bool init_done = false;
    static cudaStream_t s1;
    static cudaEvent_t evQK, evV;
    if (!init_done) {
        cudaFuncSetAttribute(gemm_tc_kernel,
                             cudaFuncAttributeMaxDynamicSharedMemorySize, GEMM_SMEM);
        cudaStreamCreateWithFlags(&s1, cudaStreamNonBlocking);
        cudaEventCreateWithFlags(&evQK, cudaEventDisableTiming);
        cudaEventCreateWithFlags(&evV, cudaEventDisableTiming);
        init_done = true;
    }

    // stream0: wsplit -> gemm(q,k) -> measure -> topk -> [wait v-chain] -> attn -> ln
    // stream1:            [after gemm_qk] gemm(v) -> vmean -> evV
    wsplit_t_kernel<<<dim3(16, 16, 3), dim3(32, 8)>>>(Wq, Wk, Wv);
    gemm_tc_kernel<<<dim3(4, 32, 2), 512, GEMM_SMEM>>>(q, k, v, bq, bk, bv, 0);
    cudaEventRecord(evQK, 0);

    cudaStreamWaitEvent(s1, evQK, 0);
    gemm_tc_kernel<<<dim3(4, 32, 1), 512, GEMM_SMEM, s1>>>(q, k, v, bq, bk, bv, 2);
    vmean_part_kernel<<<256, DMM, 0, s1>>>();
    vmean_reduce_kernel<<<Bb, DMM, 0, s1>>>();
    cudaEventRecord(evV, s1);

    measure_kernel<<<Bb * Ll / 4, 256>>>(ridx);
    topk_kernel<<<Bb * Hh, 256>>>();

    cudaStreamWaitEvent(0, evV, 0);
    attn_kernel<<<Bb * Hh * 10, 512>>>(out_attn);
    ln_kernel<<<Bb * Ll, 256>>>(q, gamma, beta, out);
}

// round 16
// speedup vs baseline: 1.4095x; 1.4095x over previous
#include <cuda_runtime.h>
#include <cuda_bf16.h>
#include <math.h>
#include <stdint.h>

#define Bb 2
#define Ll 2048
#define DMM 512
#define Hh 8
#define Dd 64
#define NUMK 40
#define NUMQ 40
#define LN_EPS 1e-5f

// ---------------- scratch (static device globals; no allocs allowed) ----------------
__device__ __align__(256) float g_qp[Bb*Ll*DMM];
__device__ __align__(256) float g_kp[Bb*Ll*DMM];
__device__ __align__(256) float g_vp[Bb*Ll*DMM];
__device__ __align__(256) float g_measure[Bb*Hh*Ll];
__device__ __align__(256) float g_vpart[Bb*128*DMM];
__device__ __align__(256) float g_vmean[Bb*DMM];
__device__ __align__(256) int   g_qidx[Bb*Hh*NUMQ];
__device__ __align__(256) int   g_slot[Bb*Hh*Ll];
__device__ __align__(256) float g_outsel[Bb*Hh*NUMQ*Dd];
// W transposed + bf16 hi/lo split: [which][N][K]
__device__ __align__(256) __nv_bfloat16 g_Wth[3*DMM*DMM];
__device__ __align__(256) __nv_bfloat16 g_Wtl[3*DMM*DMM];

// ============================ helpers ============================
__device__ __forceinline__ uint32_t smem_u32(const void* p) {
    uint32_t a;
    asm("{ .reg .u64 t; cvta.to.shared.u64 t, %1; cvt.u32.u64 %0, t; }" : "=r"(a) : "l"(p));
    return a;
}
#define SWZ128(off) ((off) ^ (((off) >> 3) & 0x70))

#define STS128(addr, a, b, c, d) \
    asm volatile("st.shared.v4.b32 [%0], {%1, %2, %3, %4};" \
                 :: "r"(addr), "r"(a), "r"(b), "r"(c), "r"(d) : "memory")

__device__ __forceinline__ void ldsm4(uint32_t& r0, uint32_t& r1, uint32_t& r2, uint32_t& r3,
                                      uint32_t addr) {
    asm volatile("ldmatrix.sync.aligned.m8n8.x4.shared.b16 {%0,%1,%2,%3}, [%4];"
                 : "=r"(r0), "=r"(r1), "=r"(r2), "=r"(r3) : "r"(addr));
}
__device__ __forceinline__ void mma16816(float* c, const uint32_t* a, uint32_t b0, uint32_t b1) {
    asm volatile(
        "mma.sync.aligned.m16n8k16.row.col.f32.bf16.bf16.f32 "
        "{%0,%1,%2,%3}, {%4,%5,%6,%7}, {%8,%9}, {%0,%1,%2,%3};"
        : "+f"(c[0]), "+f"(c[1]), "+f"(c[2]), "+f"(c[3])
        : "r"(a[0]), "r"(a[1]), "r"(a[2]), "r"(a[3]), "r"(b0), "r"(b1));
}

__device__ __forceinline__ void split2(float a, float b, uint32_t& h, uint32_t& l) {
    __nv_bfloat16 ha = __float2bfloat16(a), hb = __float2bfloat16(b);
    __nv_bfloat16 la = __float2bfloat16(a - __bfloat162float(ha));
    __nv_bfloat16 lb = __float2bfloat16(b - __bfloat162float(hb));
    __nv_bfloat162 hh(ha, hb), ll(la, lb);
    h = *reinterpret_cast<uint32_t*>(&hh);
    l = *reinterpret_cast<uint32_t*>(&ll);
}

// ---------------- W transpose + bf16 split: Wt[n][k] = W[k][n] ----------------
__global__ void wsplit_t_kernel(const float* __restrict__ Wq,
                                const float* __restrict__ Wk,
                                const float* __restrict__ Wv)
{
    int which = blockIdx.z;
    const float* W = (which == 0) ? Wq : (which == 1) ? Wk : Wv;
    __nv_bfloat16* Th = g_Wth + (size_t)which * DMM * DMM;
    __nv_bfloat16* Tl = g_Wtl + (size_t)which * DMM * DMM;
    __shared__ float tile[32][33];
    int n0 = blockIdx.x * 32, k0 = blockIdx.y * 32;
    int x = threadIdx.x, y = threadIdx.y;   // 32 x 8
#pragma unroll
    for (int yy = 0; yy < 32; yy += 8)
        tile[y + yy][x] = W[(size_t)(k0 + y + yy) * DMM + n0 + x];
    __syncthreads();
#pragma unroll
    for (int yy = 0; yy < 32; yy += 8) {
        int n = n0 + y + yy;
        float f = tile[x][y + yy];           // = W[k0+x][n]
        __nv_bfloat16 h = __float2bfloat16(f);
        Th[(size_t)n * DMM + k0 + x] = h;
        Tl[(size_t)n * DMM + k0 + x] = __float2bfloat16(f - __bfloat162float(h));
    }
}

// ---------------- HMMA GEMM: 512 threads, 16 warps of 32x32 ----------------
#define OFF_AH 0
#define OFF_AL 16384
#define OFF_BH 32768
#define OFF_BL 49152
#define GEMM_SMEM 66560

__global__ void __launch_bounds__(512, 1)
gemm_tc_kernel(const float* __restrict__ qin, const float* __restrict__ kin,
               const float* __restrict__ vin,
               const float* __restrict__ bq, const float* __restrict__ bk,
               const float* __restrict__ bv, int zbase)
{
    extern __shared__ char dsm[];

    int which = blockIdx.z + zbase;
    const float* A    = (which == 0) ? qin : (which == 1) ? kin : vin;
    const float* bias = (which == 0) ? bq  : (which == 1) ? bk  : bv;
    float* C          = (which == 0) ? g_qp : (which == 1) ? g_kp : g_vp;
    const __nv_bfloat16* Bh = g_Wth + (size_t)which * DMM * DMM;
    const __nv_bfloat16* Bl = g_Wtl + (size_t)which * DMM * DMM;

    int tid = threadIdx.x, wid = tid >> 5, lane = tid & 31;
    int m0 = blockIdx.y * 128, n0 = blockIdx.x * 128;
    int wm = wid & 3, wn = wid >> 2;

    uint32_t sb = (smem_u32(dsm) + 1023u) & ~1023u;

    uint32_t soff[2];
    int rr[2], cc[2];
#pragma unroll
    for (int jj = 0; jj < 2; jj++) {
        int i = tid + 512 * jj;
        rr[jj] = i >> 3;
        cc[jj] = i & 7;
        soff[jj] = SWZ128((uint32_t)(rr[jj] * 128 + cc[jj] * 16));
    }

    uint32_t a_off[2], b_off[2];
#pragma unroll
    for (int mt = 0; mt < 2; mt++)
        a_off[mt] = (uint32_t)((wm * 32 + mt * 16 + (lane & 15)) * 128);
#pragma unroll
    for (int bt = 0; bt < 2; bt++)
        b_off[bt] = (uint32_t)((wn * 32 + bt * 16 + (lane & 15)) * 128);
    int lhalf = lane >> 4;

    float acc[2][4][4];
#pragma unroll
    for (int i = 0; i < 2; i++)
#pragma unroll
        for (int j = 0; j < 4; j++)
#pragma unroll
            for (int c = 0; c < 4; c++) acc[i][j][c] = 0.f;

    float4 fa[4];
    uint4 vbh[2], vbl[2];

#pragma unroll
    for (int jj = 0; jj < 2; jj++) {
        const float* pa = A + (size_t)(m0 + rr[jj]) * DMM + cc[jj] * 8;
        fa[2*jj]   = *(const float4*)pa;
        fa[2*jj+1] = *(const float4*)(pa + 4);
        vbh[jj] = *(const uint4*)(Bh + (size_t)(n0 + rr[jj]) * DMM + cc[jj] * 8);
        vbl[jj] = *(const uint4*)(Bl + (size_t)(n0 + rr[jj]) * DMM + cc[jj] * 8);
    }

    for (int kt = 0; kt < 8; kt++) {
#pragma unroll
        for (int jj = 0; jj < 2; jj++) {
            uint32_t h0,h1,h2,h3,l0,l1,l2,l3;
            split2(fa[2*jj].x,   fa[2*jj].y,   h0, l0);
            split2(fa[2*jj].z,   fa[2*jj].w,   h1, l1);
            split2(fa[2*jj+1].x, fa[2*jj+1].y, h2, l2);
            split2(fa[2*jj+1].z, fa[2*jj+1].w, h3, l3);
            STS128(sb + OFF_AH + soff[jj], h0, h1, h2, h3);
            STS128(sb + OFF_AL + soff[jj], l0, l1, l2, l3);
            STS128(sb + OFF_BH + soff[jj], vbh[jj].x, vbh[jj].y, vbh[jj].z, vbh[jj].w);
            STS128(sb + OFF_BL + soff[jj], vbl[jj].x, vbl[jj].y, vbl[jj].z, vbl[jj].w);
        }
        __syncthreads();

        if (kt < 7) {
            int kb = (kt + 1) * 64;
#pragma unroll
            for (int jj = 0; jj < 2; jj++) {
                const float* pa = A + (size_t)(m0 + rr[jj]) * DMM + kb + cc[jj] * 8;
                fa[2*jj]   = *(const float4*)pa;
                fa[2*jj+1] = *(const float4*)(pa + 4);
                vbh[jj] = *(const uint4*)(Bh + (size_t)(n0 + rr[jj]) * DMM + kb + cc[jj] * 8);
                vbl[jj] = *(const uint4*)(Bl + (size_t)(n0 + rr[jj]) * DMM + kb + cc[jj] * 8);
            }
        }

#pragma unroll
        for (int ks = 0; ks < 4; ks++) {
            uint32_t chunk = (uint32_t)((2*ks + lhalf) * 16);
            uint32_t ah[2][4], al[2][4];
#pragma unroll
            for (int mt = 0; mt < 2; mt++) {
                uint32_t sw = SWZ128(a_off[mt] + chunk);
                ldsm4(ah[mt][0], ah[mt][1], ah[mt][2], ah[mt][3], sb + OFF_AH + sw);
                ldsm4(al[mt][0], al[mt][1], al[mt][2], al[mt][3], sb + OFF_AL + sw);
            }
            uint32_t bh[2][4], bl[2][4];
#pragma unroll
            for (int bt = 0; bt < 2; bt++) {
                uint32_t sw = SWZ128(b_off[bt] + chunk);
                ldsm4(bh[bt][0], bh[bt][1], bh[bt][2], bh[bt][3], sb + OFF_BH + sw);
                ldsm4(bl[bt][0], bl[bt][1], bl[bt][2], bl[bt][3], sb + OFF_BL + sw);
            }
#pragma unroll
            for (int mt = 0; mt < 2; mt++)
#pragma unroll
                for (int nt = 0; nt < 4; nt++) {
                    int bt = nt >> 1, hi = nt & 1;
                    mma16816(acc[mt][nt], ah[mt], bh[bt][hi], bh[bt][hi+2]);
                }
#pragma unroll
            for (int mt = 0; mt < 2; mt++)
#pragma unroll
                for (int nt = 0; nt < 4; nt++) {
                    int bt = nt >> 1, hi = nt & 1;
                    mma16816(acc[mt][nt], ah[mt], bl[bt][hi], bl[bt][hi+2]);
                }
#pragma unroll
            for (int mt = 0; mt < 2; mt++)
#pragma unroll
                for (int nt = 0; nt < 4; nt++) {
                    int bt = nt >> 1, hi = nt & 1;
                    mma16816(acc[mt][nt], al[mt], bh[bt][hi], bh[bt][hi+2]);
                }
        }
        __syncthreads();
    }

#pragma unroll
    for (int mt = 0; mt < 2; mt++) {
        int mrow = m0 + wm*32 + mt*16 + (lane >> 2);
#pragma unroll
        for (int nt = 0; nt < 4; nt++) {
            int ncol = n0 + wn*32 + nt*8 + (lane & 3)*2;
            float b0 = bias[ncol], b1 = bias[ncol + 1];
            float2 v0 = make_float2(acc[mt][nt][0] + b0, acc[mt][nt][1] + b1);
            float2 v1 = make_float2(acc[mt][nt][2] + b0, acc[mt][nt][3] + b1);
            *(float2*)(C + (size_t)mrow * DMM + ncol)       = v0;
            *(float2*)(C + (size_t)(mrow + 8) * DMM + ncol) = v1;
        }
    }
}

// ---------------- v_mean (two-stage, deterministic) ----------------
__global__ void vmean_part_kernel() {
    int blk = blockIdx.x;               // 256
    int b = blk >> 7, j = blk & 127;    // 16 rows each
    int c = threadIdx.x;                // 512
    int base = j * 16;
    const float* p = &g_vp[((size_t)b*Ll + base)*DMM + c];
    float s0 = 0.f, s1 = 0.f, s2 = 0.f, s3 = 0.f;
#pragma unroll
    for (int l = 0; l < 16; l += 4) {
        s0 += p[(size_t)(l  )*DMM];
        s1 += p[(size_t)(l+1)*DMM];
        s2 += p[(size_t)(l+2)*DMM];
        s3 += p[(size_t)(l+3)*DMM];
    }
    g_vpart[(size_t)blk*DMM + c] = (s0 + s1) + (s2 + s3);
}
__global__ void vmean_reduce_kernel() {
    int b = blockIdx.x; int c = threadIdx.x;
    const float* p = &g_vpart[(size_t)b*128*DMM + c];
    float s[16];
#pragma unroll
    for (int i = 0; i < 16; i++) s[i] = p[(size_t)i*DMM];
#pragma unroll
    for (int j = 16; j < 128; j += 16)
#pragma unroll
        for (int i = 0; i < 16; i++) s[i] += p[(size_t)(j+i)*DMM];
    float t = 0.f;
#pragma unroll
    for (int i = 0; i < 16; i++) t += s[i];
    g_vmean[b*DMM + c] = t * (1.0f / Ll);
}

// ---------------- pre + measure: 2 warps per (b,l), 20 samples each ----------------
__global__ __launch_bounds__(256) void measure_kernel(const int* __restrict__ ridx) {
    __shared__ float smx[4][2][8], ssm[4][2][8];
    int tid = threadIdx.x, warp = tid >> 5, lane = tid & 31;
    int p = warp >> 1, half = warp & 1;
    int gp = blockIdx.x * 4 + p;           // 0..4095
    int l = gp & (Ll - 1), b = gp >> 11;
    const float4* qrow = (const float4*)&g_qp[((size_t)b*Ll + l) * DMM];
    float4 q0 = qrow[lane*4+0], q1 = qrow[lane*4+1], q2 = qrow[lane*4+2], q3 = qrow[lane*4+3];
    int idx = ridx[l*NUMK + half*20 + (lane >= 20 ? lane - 20 : lane)];
    float mx = -INFINITY, sm = 0.f;
#pragma unroll 4
    for (int j = 0; j < 20; j++) {
        int ki = __shfl_sync(0xffffffffu, idx, j);
        const float4* kr = (const float4*)&g_kp[((size_t)b*Ll + ki) * DMM];
        float4 k0 = kr[lane*4+0], k1 = kr[lane*4+1], k2 = kr[lane*4+2], k3 = kr[lane*4+3];
        float pv = q0.x*k0.x + q0.y*k0.y + q0.z*k0.z + q0.w*k0.w
                 + q1.x*k1.x + q1.y*k1.y + q1.z*k1.z + q1.w*k1.w
                 + q2.x*k2.x + q2.y*k2.y + q2.z*k2.z + q2.w*k2.w
                 + q3.x*k3.x + q3.y*k3.y + q3.z*k3.z + q3.w*k3.w;
        pv += __shfl_xor_sync(0xffffffffu, pv, 1);
        pv += __shfl_xor_sync(0xffffffffu, pv, 2);
        mx = fmaxf(mx, pv);
        sm += pv;
    }
    if ((lane & 3) == 0) {
        smx[p][half][lane >> 2] = mx;
        ssm[p][half][lane >> 2] = sm;
    }
    __syncthreads();
    if (tid < 32) {
        int pp = tid >> 3, h = tid & 7;
        float m = fmaxf(smx[pp][0][h], smx[pp][1][h]);
        float s = ssm[pp][0][h] + ssm[pp][1][h];
        int gpp = blockIdx.x * 4 + pp;
        int ll = gpp & (Ll - 1), bb = gpp >> 11;
        g_measure[((size_t)bb*Hh + h)*Ll + ll] = m - s * (1.0f / Ll);
    }
}

// ---------------- exact top-40 per (b,h): slot init + select + scatter (R12 proven) ----------------
__global__ __launch_bounds__(256) void topk_kernel() {
    int bh = blockIdx.x, t = threadIdx.x;
    for (int i = t; i < Ll; i += 256) g_slot[(size_t)bh*Ll + i] = -1;
    float v[8];
    const float* src = g_measure + (size_t)bh * Ll;
#pragma unroll
    for (int m = 0; m < 8; m++) v[m] = src[t + 256*m];
    __shared__ float swv[8];
    __shared__ int   swi[8];
    __shared__ int   s_best;
    __shared__ int   qsel[NUMQ];
    for (int s = 0; s < NUMQ; s++) {
        float bv = v[0]; int bi = t;
#pragma unroll
        for (int m = 1; m < 8; m++) {
            int i = t + 256*m;
            if (v[m] > bv || (v[m] == bv && i < bi)) { bv = v[m]; bi = i; }
        }
#pragma unroll
        for (int o = 16; o; o >>= 1) {
            float ov = __shfl_xor_sync(0xffffffffu, bv, o);
            int   oi = __shfl_xor_sync(0xffffffffu, bi, o);
            if (ov > bv || (ov == bv && oi < bi)) { bv = ov; bi = oi; }
        }
        if ((t & 31) == 0) { swv[t >> 5] = bv; swi[t >> 5] = bi; }
        __syncthreads();
        if (t == 0) {
            float rv = swv[0]; int ri = swi[0];
#pragma unroll
            for (int w = 1; w < 8; w++)
                if (swv[w] > rv || (swv[w] == rv && swi[w] < ri)) { rv = swv[w]; ri = swi[w]; }
            g_qidx[bh*NUMQ + s] = ri;
            qsel[s] = ri;
            s_best = ri;
        }
        __syncthreads();
        int ib = s_best;
        if ((ib & 255) == t) v[ib >> 8] = -INFINITY;
    }
    if (t < NUMQ) g_slot[(size_t)bh * Ll + qsel[t]] = t;
}

// ---------------- attention: 512 threads, block per (b,h,group-of-8-q), dynamic smem ----------------
#define ATTN_SMEM (8*Ll*4 + 8*Dd*4 + 8*8*Dd*4 + 64 + 32)
__global__ void __launch_bounds__(512)
attn_kernel(float* __restrict__ out_attn)
{
    extern __shared__ char asm_[];
    float (*sc)[Ll]      = (float (*)[Ll])asm_;                       // 8 x 2048
    float (*qs)[Dd]      = (float (*)[Dd])(asm_ + 8*Ll*4);            // 8 x 64
    float (*pvs)[8][Dd]  = (float (*)[8][Dd])(asm_ + 8*Ll*4 + 8*Dd*4);// [part][q][d]
    float* red           = (float*)(asm_ + 8*Ll*4 + 8*Dd*4 + 8*8*Dd*4);
    int*   qix           = (int*)(asm_ + 8*Ll*4 + 8*Dd*4 + 8*8*Dd*4 + 64);

    int blk = blockIdx.x;                  // (b*Hh + h)*5 + g
    int g = blk % 5;
    int h = (blk / 5) % Hh;
    int b = blk / (5 * Hh);
    int tid = threadIdx.x;
    int lane = tid & 31, w = tid >> 5;     // 16 warps
    if (tid < 8) qix[tid] = g_qidx[(b*Hh + h)*NUMQ + g*8 + tid];
    __syncthreads();
    {
        int qq = tid >> 6, d = tid & 63;   // 512 threads cover 8x64
        qs[qq][d] = g_qp[((size_t)b*Ll + qix[qq])*DMM + h*Dd + d];
    }
    __syncthreads();
    const float scale = 0.125f;

    // scores: 4 lanes per key, q vectors from smem (broadcast across quads)
    int quarter = lane & 3, keyoff = lane >> 2;
    for (int pass = 0; pass < 16; pass++) {
        int j = w*128 + pass*8 + keyoff;
        const float4* kr = (const float4*)&g_kp[((size_t)b*Ll + j)*DMM + h*Dd + quarter*16];
        float4 k0 = kr[0], k1 = kr[1], k2 = kr[2], k3 = kr[3];
        float p[8];
#pragma unroll
        for (int q = 0; q < 8; q++) {
            const float4* qp4 = (const float4*)&qs[q][quarter*16];
            float4 a0 = qp4[0], a1 = qp4[1], a2 = qp4[2], a3 = qp4[3];
            p[q] = a0.x*k0.x + a0.y*k0.y + a0.z*k0.z + a0.w*k0.w
                 + a1.x*k1.x + a1.y*k1.y + a1.z*k1.z + a1.w*k1.w
                 + a2.x*k2.x + a2.y*k2.y + a2.z*k2.z + a2.w*k2.w
                 + a3.x*k3.x + a3.y*k3.y + a3.z*k3.z + a3.w*k3.w;
            p[q] += __shfl_xor_sync(0xffffffffu, p[q], 1);
            p[q] += __shfl_xor_sync(0xffffffffu, p[q], 2);
        }
        if (quarter == 0) {
#pragma unroll
            for (int q = 0; q < 8; q++) sc[q][j] = p[q] * scale;
        }
    }
    __syncthreads();
#pragma unroll
    for (int q = 0; q < 8; q++) {
        float m = -INFINITY;
        for (int j = tid; j < Ll; j += 512) m = fmaxf(m, sc[q][j]);
#pragma unroll
        for (int o = 16; o; o >>= 1) m = fmaxf(m, __shfl_xor_sync(0xffffffffu, m, o));
        if (lane == 0) red[w] = m;
        __syncthreads();
        m = red[0];
#pragma unroll
        for (int i = 1; i < 16; i++) m = fmaxf(m, red[i]);
        __syncthreads();
        float s = 0.f;
        for (int j = tid; j < Ll; j += 512) { float e = expf(sc[q][j] - m); sc[q][j] = e; s += e; }
#pragma unroll
        for (int o = 16; o; o >>= 1) s += __shfl_xor_sync(0xffffffffu, s, o);
        if (lane == 0) red[w] = s;
        __syncthreads();
        float tot = red[0];
#pragma unroll
        for (int i = 1; i < 16; i++) tot += red[i];
        float inv = 1.0f / tot;
        size_t aoff = ((size_t)(b*Hh + h)*NUMQ + g*8 + q) * Ll;
        for (int j = tid; j < Ll; j += 512) {
            float p = sc[q][j] * inv;
            sc[q][j] = p;
            out_attn[aoff + j] = p;
        }
        __syncthreads();
    }
    // PV: 8 partitions over j, 64 d-threads each, 8 q accumulators
    int d = tid & 63, part = tid >> 6;     // part 0..7
    float a[8];
#pragma unroll
    for (int q = 0; q < 8; q++) a[q] = 0.f;
    int j0 = part * 256;
    const float* vbase = &g_vp[((size_t)b*Ll + j0)*DMM + h*Dd + d];
    for (int jb = 0; jb < 256; jb++) {
        float vv = vbase[(size_t)jb*DMM];
        int j = j0 + jb;
#pragma unroll
        for (int q = 0; q < 8; q++) a[q] += sc[q][j]*vv;
    }
#pragma unroll
    for (int q = 0; q < 8; q++) pvs[part][q][d] = a[q];
    __syncthreads();
    if (part == 0) {
#pragma unroll
        for (int q = 0; q < 8; q++) {
            float r = 0.f;
#pragma unroll
            for (int pp = 0; pp < 8; pp++) r += pvs[pp][q][d];
            g_outsel[((size_t)((b*Hh + h)*NUMQ) + g*8 + q)*Dd + d] = r;
        }
    }
}

// ---------------- residual + layernorm (vmean/outsel compose) ----------------
__global__ __launch_bounds__(256) void ln_kernel(const float* __restrict__ qin,
                                                 const float* __restrict__ gamma,
                                                 const float* __restrict__ beta,
                                                 float* __restrict__ out)
{
    int row = blockIdx.x;            // Bb*Ll
    int b = row >> 11, l = row & (Ll - 1);
    int tid = threadIdx.x;
    __shared__ float sm[8], sm2[8];
    __shared__ int slots[8];
    if (tid < 8) slots[tid] = g_slot[(size_t)(b*Hh + tid)*Ll + l];
    __syncthreads();
    const float* qr = qin + (size_t)row * DMM;
    int c0 = tid, c1 = tid + 256;
    int h0 = c0 >> 6, h1 = c1 >> 6;
    int s0i = slots[h0], s1i = slots[h1];
    float ctx0 = (s0i >= 0)
        ? g_outsel[((size_t)((b*Hh + h0)*NUMQ) + s0i)*Dd + (c0 & 63)]
        : g_vmean[b*DMM + c0];
    float ctx1 = (s1i >= 0)
        ? g_outsel[((size_t)((b*Hh + h1)*NUMQ) + s1i)*Dd + (c1 & 63)]
        : g_vmean[b*DMM + c1];
    float v0 = ctx0 + qr[c0];
    float v1 = ctx1 + qr[c1];
    int lane = tid & 31, w = tid >> 5;
    float s = v0 + v1;
#pragma unroll
    for (int o = 16; o; o >>= 1) s += __shfl_xor_sync(0xffffffffu, s, o);
    if (lane == 0) sm[w] = s;
    __syncthreads();
    float mean = (sm[0]+sm[1]+sm[2]+sm[3]+sm[4]+sm[5]+sm[6]+sm[7]) * (1.0f / DMM);
    float d0 = v0 - mean, d1 = v1 - mean;
    float s2 = d0*d0 + d1*d1;
#pragma unroll
    for (int o = 16; o; o >>= 1) s2 += __shfl_xor_sync(0xffffffffu, s2, o);
    if (lane == 0) sm2[w] = s2;
    __syncthreads();
    float var = (sm2[0]+sm2[1]+sm2[2]+sm2[3]+sm2[4]+sm2[5]+sm2[6]+sm2[7]) * (1.0f / DMM);
    float invstd = rsqrtf(var + LN_EPS);
    out[(size_t)row*DMM + c0] = d0 * invstd * gamma[c0] + beta[c0];
    out[(size_t)row*DMM + c1] = d1 * invstd * gamma[c1] + beta[c1];
}

// ---------------- launch ----------------
extern "C" void kernel_launch(void* const* d_in, const int* in_sizes, int n_in,
                              void* d_out, int out_size)
{
    const float* q     = (const float*)d_in[0];
    const float* k     = (const float*)d_in[1];
    const float* v     = (const float*)d_in[2];
    const float* Wq    = (const float*)d_in[3];
    const float* bq    = (const float*)d_in[4];
    const float* Wk    = (const float*)d_in[5];
    const float* bk    = (const float*)d_in[6];
    const float* Wv    = (const float*)d_in[7];
    const float* bv    = (const float*)d_in[8];
    const float* gamma = (const float*)d_in[9];
    const float* beta  = (const float*)d_in[10];
    const int*   ridx  = (const int*)d_in[11];
    float* out      = (float*)d_out;
    float* out_attn = out + (size_t)Bb * Ll * DMM;

    static bool init_done = false;
    static cudaStream_t s1;
    static cudaEvent_t evQK, evV;
    if (!init_done) {
        cudaFuncSetAttribute(gemm_tc_kernel,
                             cudaFuncAttributeMaxDynamicSharedMemorySize, GEMM_SMEM);
        cudaFuncSetAttribute(attn_kernel,
                             cudaFuncAttributeMaxDynamicSharedMemorySize, ATTN_SMEM);
        cudaStreamCreateWithFlags(&s1, cudaStreamNonBlocking);
        cudaEventCreateWithFlags(&evQK, cudaEventDisableTiming);
        cudaEventCreateWithFlags(&evV, cudaEventDisableTiming);
        init_done = true;
    }

    // stream0: wsplit -> gemm(q,k) -> measure -> topk -> [wait v-chain] -> attn -> ln
    // stream1:            [after gemm_qk] gemm(v) -> vmean -> evV
    wsplit_t_kernel<<<dim3(16, 16, 3), dim3(32, 8)>>>(Wq, Wk, Wv);
    gemm_tc_kernel<<<dim3(4, 32, 2), 512, GEMM_SMEM>>>(q, k, v, bq, bk, bv, 0);
    cudaEventRecord(evQK, 0);

    cudaStreamWaitEvent(s1, evQK, 0);
    gemm_tc_kernel<<<dim3(4, 32, 1), 512, GEMM_SMEM, s1>>>(q, k, v, bq, bk, bv, 2);
    vmean_part_kernel<<<256, DMM, 0, s1>>>();
    vmean_reduce_kernel<<<Bb, DMM, 0, s1>>>();
    cudaEventRecord(evV, s1);

    measure_kernel<<<Bb * Ll / 4, 256>>>(ridx);
    topk_kernel<<<Bb * Hh, 256>>>();

    cudaStreamWaitEvent(0, evV, 0);
    attn_kernel<<<Bb * Hh * 5, 512, ATTN_SMEM>>>(out_attn);
    ln_kernel<<<Bb * Ll, 256>>>(q, gamma, beta, out);
}

// round 17
// speedup vs baseline: 1.6399x; 1.1635x over previous
#include <cuda_runtime.h>
#include <cuda_bf16.h>
#include <math.h>
#include <stdint.h>

#define Bb 2
#define Ll 2048
#define DMM 512
#define Hh 8
#define Dd 64
#define NUMK 40
#define NUMQ 40
#define LN_EPS 1e-5f

// ---------------- scratch (static device globals; no allocs allowed) ----------------
__device__ __align__(256) float g_qp[Bb*Ll*DMM];
__device__ __align__(256) float g_kp[Bb*Ll*DMM];
__device__ __align__(256) float g_vp[Bb*Ll*DMM];
__device__ __align__(256) float g_measure[Bb*Hh*Ll];
__device__ __align__(256) float g_vpart[Bb*128*DMM];
__device__ __align__(256) float g_vmean[Bb*DMM];
__device__ __align__(256) int   g_qidx[Bb*Hh*NUMQ];
__device__ __align__(256) int   g_slot[Bb*Hh*Ll];
__device__ __align__(256) float g_outsel[Bb*Hh*NUMQ*Dd];
// W transposed + bf16 hi/lo split: [which][N][K]
__device__ __align__(256) __nv_bfloat16 g_Wth[3*DMM*DMM];
__device__ __align__(256) __nv_bfloat16 g_Wtl[3*DMM*DMM];

// ============================ helpers ============================
__device__ __forceinline__ uint32_t smem_u32(const void* p) {
    uint32_t a;
    asm("{ .reg .u64 t; cvta.to.shared.u64 t, %1; cvt.u32.u64 %0, t; }" : "=r"(a) : "l"(p));
    return a;
}
#define SWZ128(off) ((off) ^ (((off) >> 3) & 0x70))

#define STS128(addr, a, b, c, d) \
    asm volatile("st.shared.v4.b32 [%0], {%1, %2, %3, %4};" \
                 :: "r"(addr), "r"(a), "r"(b), "r"(c), "r"(d) : "memory")

__device__ __forceinline__ void ldsm4(uint32_t& r0, uint32_t& r1, uint32_t& r2, uint32_t& r3,
                                      uint32_t addr) {
    asm volatile("ldmatrix.sync.aligned.m8n8.x4.shared.b16 {%0,%1,%2,%3}, [%4];"
                 : "=r"(r0), "=r"(r1), "=r"(r2), "=r"(r3) : "r"(addr));
}
__device__ __forceinline__ void mma16816(float* c, const uint32_t* a, uint32_t b0, uint32_t b1) {
    asm volatile(
        "mma.sync.aligned.m16n8k16.row.col.f32.bf16.bf16.f32 "
        "{%0,%1,%2,%3}, {%4,%5,%6,%7}, {%8,%9}, {%0,%1,%2,%3};"
        : "+f"(c[0]), "+f"(c[1]), "+f"(c[2]), "+f"(c[3])
        : "r"(a[0]), "r"(a[1]), "r"(a[2]), "r"(a[3]), "r"(b0), "r"(b1));
}

__device__ __forceinline__ void split2(float a, float b, uint32_t& h, uint32_t& l) {
    __nv_bfloat16 ha = __float2bfloat16(a), hb = __float2bfloat16(b);
    __nv_bfloat16 la = __float2bfloat16(a - __bfloat162float(ha));
    __nv_bfloat16 lb = __float2bfloat16(b - __bfloat162float(hb));
    __nv_bfloat162 hh(ha, hb), ll(la, lb);
    h = *reinterpret_cast<uint32_t*>(&hh);
    l = *reinterpret_cast<uint32_t*>(&ll);
}

// ---------------- W transpose + bf16 split: Wt[n][k] = W[k][n] ----------------
__global__ void wsplit_t_kernel(const float* __restrict__ Wq,
                                const float* __restrict__ Wk,
                                const float* __restrict__ Wv)
{
    int which = blockIdx.z;
    const float* W = (which == 0) ? Wq : (which == 1) ? Wk : Wv;
    __nv_bfloat16* Th = g_Wth + (size_t)which * DMM * DMM;
    __nv_bfloat16* Tl = g_Wtl + (size_t)which * DMM * DMM;
    __shared__ float tile[32][33];
    int n0 = blockIdx.x * 32, k0 = blockIdx.y * 32;
    int x = threadIdx.x, y = threadIdx.y;   // 32 x 8
#pragma unroll
    for (int yy = 0; yy < 32; yy += 8)
        tile[y + yy][x] = W[(size_t)(k0 + y + yy) * DMM + n0 + x];
    __syncthreads();
#pragma unroll
    for (int yy = 0; yy < 32; yy += 8) {
        int n = n0 + y + yy;
        float f = tile[x][y + yy];           // = W[k0+x][n]
        __nv_bfloat16 h = __float2bfloat16(f);
        Th[(size_t)n * DMM + k0 + x] = h;
        Tl[(size_t)n * DMM + k0 + x] = __float2bfloat16(f - __bfloat162float(h));
    }
}

// ---------------- HMMA GEMM: 512 threads, 16 warps of 32x32 ----------------
#define OFF_AH 0
#define OFF_AL 16384
#define OFF_BH 32768
#define OFF_BL 49152
#define GEMM_SMEM 66560

__global__ void __launch_bounds__(512, 1)
gemm_tc_kernel(const float* __restrict__ qin, const float* __restrict__ kin,
               const float* __restrict__ vin,
               const float* __restrict__ bq, const float* __restrict__ bk,
               const float* __restrict__ bv, int zbase)
{
    extern __shared__ char dsm[];

    int which = blockIdx.z + zbase;
    const float* A    = (which == 0) ? qin : (which == 1) ? kin : vin;
    const float* bias = (which == 0) ? bq  : (which == 1) ? bk  : bv;
    float* C          = (which == 0) ? g_qp : (which == 1) ? g_kp : g_vp;
    const __nv_bfloat16* Bh = g_Wth + (size_t)which * DMM * DMM;
    const __nv_bfloat16* Bl = g_Wtl + (size_t)which * DMM * DMM;

    int tid = threadIdx.x, wid = tid >> 5, lane = tid & 31;
    int m0 = blockIdx.y * 128, n0 = blockIdx.x * 128;
    int wm = wid & 3, wn = wid >> 2;

    uint32_t sb = (smem_u32(dsm) + 1023u) & ~1023u;

    uint32_t soff[2];
    int rr[2], cc[2];
#pragma unroll
    for (int jj = 0; jj < 2; jj++) {
        int i = tid + 512 * jj;
        rr[jj] = i >> 3;
        cc[jj] = i & 7;
        soff[jj] = SWZ128((uint32_t)(rr[jj] * 128 + cc[jj] * 16));
    }

    uint32_t a_off[2], b_off[2];
#pragma unroll
    for (int mt = 0; mt < 2; mt++)
        a_off[mt] = (uint32_t)((wm * 32 + mt * 16 + (lane & 15)) * 128);
#pragma unroll
    for (int bt = 0; bt < 2; bt++)
        b_off[bt] = (uint32_t)((wn * 32 + bt * 16 + (lane & 15)) * 128);
    int lhalf = lane >> 4;

    float acc[2][4][4];
#pragma unroll
    for (int i = 0; i < 2; i++)
#pragma unroll
        for (int j = 0; j < 4; j++)
#pragma unroll
            for (int c = 0; c < 4; c++) acc[i][j][c] = 0.f;

    float4 fa[4];
    uint4 vbh[2], vbl[2];

#pragma unroll
    for (int jj = 0; jj < 2; jj++) {
        const float* pa = A + (size_t)(m0 + rr[jj]) * DMM + cc[jj] * 8;
        fa[2*jj]   = *(const float4*)pa;
        fa[2*jj+1] = *(const float4*)(pa + 4);
        vbh[jj] = *(const uint4*)(Bh + (size_t)(n0 + rr[jj]) * DMM + cc[jj] * 8);
        vbl[jj] = *(const uint4*)(Bl + (size_t)(n0 + rr[jj]) * DMM + cc[jj] * 8);
    }

    for (int kt = 0; kt < 8; kt++) {
#pragma unroll
        for (int jj = 0; jj < 2; jj++) {
            uint32_t h0,h1,h2,h3,l0,l1,l2,l3;
            split2(fa[2*jj].x,   fa[2*jj].y,   h0, l0);
            split2(fa[2*jj].z,   fa[2*jj].w,   h1, l1);
            split2(fa[2*jj+1].x, fa[2*jj+1].y, h2, l2);
            split2(fa[2*jj+1].z, fa[2*jj+1].w, h3, l3);
            STS128(sb + OFF_AH + soff[jj], h0, h1, h2, h3);
            STS128(sb + OFF_AL + soff[jj], l0, l1, l2, l3);
            STS128(sb + OFF_BH + soff[jj], vbh[jj].x, vbh[jj].y, vbh[jj].z, vbh[jj].w);
            STS128(sb + OFF_BL + soff[jj], vbl[jj].x, vbl[jj].y, vbl[jj].z, vbl[jj].w);
        }
        __syncthreads();

        if (kt < 7) {
            int kb = (kt + 1) * 64;
#pragma unroll
            for (int jj = 0; jj < 2; jj++) {
                const float* pa = A + (size_t)(m0 + rr[jj]) * DMM + kb + cc[jj] * 8;
                fa[2*jj]   = *(const float4*)pa;
                fa[2*jj+1] = *(const float4*)(pa + 4);
                vbh[jj] = *(const uint4*)(Bh + (size_t)(n0 + rr[jj]) * DMM + kb + cc[jj] * 8);
                vbl[jj] = *(const uint4*)(Bl + (size_t)(n0 + rr[jj]) * DMM + kb + cc[jj] * 8);
            }
        }

#pragma unroll
        for (int ks = 0; ks < 2; ks++) { }  // (no-op placeholder removed below)
#pragma unroll
        for (int ks = 0; ks < 4; ks++) {
            uint32_t chunk = (uint32_t)((2*ks + lhalf) * 16);
            uint32_t ah[2][4], al[2][4];
#pragma unroll
            for (int mt = 0; mt < 2; mt++) {
                uint32_t sw = SWZ128(a_off[mt] + chunk);
                ldsm4(ah[mt][0], ah[mt][1], ah[mt][2], ah[mt][3], sb + OFF_AH + sw);
                ldsm4(al[mt][0], al[mt][1], al[mt][2], al[mt][3], sb + OFF_AL + sw);
            }
            uint32_t bh[2][4], bl[2][4];
#pragma unroll
            for (int bt = 0; bt < 2; bt++) {
                uint32_t sw = SWZ128(b_off[bt] + chunk);
                ldsm4(bh[bt][0], bh[bt][1], bh[bt][2], bh[bt][3], sb + OFF_BH + sw);
                ldsm4(bl[bt][0], bl[bt][1], bl[bt][2], bl[bt][3], sb + OFF_BL + sw);
            }
#pragma unroll
            for (int mt = 0; mt < 2; mt++)
#pragma unroll
                for (int nt = 0; nt < 4; nt++) {
                    int bt = nt >> 1, hi = nt & 1;
                    mma16816(acc[mt][nt], ah[mt], bh[bt][hi], bh[bt][hi+2]);
                }
#pragma unroll
            for (int mt = 0; mt < 2; mt++)
#pragma unroll
                for (int nt = 0; nt < 4; nt++) {
                    int bt = nt >> 1, hi = nt & 1;
                    mma16816(acc[mt][nt], ah[mt], bl[bt][hi], bl[bt][hi+2]);
                }
#pragma unroll
            for (int mt = 0; mt < 2; mt++)
#pragma unroll
                for (int nt = 0; nt < 4; nt++) {
                    int bt = nt >> 1, hi = nt & 1;
                    mma16816(acc[mt][nt], al[mt], bh[bt][hi], bh[bt][hi+2]);
                }
        }
        __syncthreads();
    }

#pragma unroll
    for (int mt = 0; mt < 2; mt++) {
        int mrow = m0 + wm*32 + mt*16 + (lane >> 2);
#pragma unroll
        for (int nt = 0; nt < 4; nt++) {
            int ncol = n0 + wn*32 + nt*8 + (lane & 3)*2;
            float b0 = bias[ncol], b1 = bias[ncol + 1];
            float2 v0 = make_float2(acc[mt][nt][0] + b0, acc[mt][nt][1] + b1);
            float2 v1 = make_float2(acc[mt][nt][2] + b0, acc[mt][nt][3] + b1);
            *(float2*)(C + (size_t)mrow * DMM + ncol)       = v0;
            *(float2*)(C + (size_t)(mrow + 8) * DMM + ncol) = v1;
        }
    }
}

// ---------------- v_mean (two-stage, deterministic) ----------------
__global__ void vmean_part_kernel() {
    int blk = blockIdx.x;               // 256
    int b = blk >> 7, j = blk & 127;    // 16 rows each
    int c = threadIdx.x;                // 512
    int base = j * 16;
    const float* p = &g_vp[((size_t)b*Ll + base)*DMM + c];
    float s0 = 0.f, s1 = 0.f, s2 = 0.f, s3 = 0.f;
#pragma unroll
    for (int l = 0; l < 16; l += 4) {
        s0 += p[(size_t)(l  )*DMM];
        s1 += p[(size_t)(l+1)*DMM];
        s2 += p[(size_t)(l+2)*DMM];
        s3 += p[(size_t)(l+3)*DMM];
    }
    g_vpart[(size_t)blk*DMM + c] = (s0 + s1) + (s2 + s3);
}
__global__ void vmean_reduce_kernel() {
    int b = blockIdx.x; int c = threadIdx.x;
    const float* p = &g_vpart[(size_t)b*128*DMM + c];
    float s[16];
#pragma unroll
    for (int i = 0; i < 16; i++) s[i] = p[(size_t)i*DMM];
#pragma unroll
    for (int j = 16; j < 128; j += 16)
#pragma unroll
        for (int i = 0; i < 16; i++) s[i] += p[(size_t)(j+i)*DMM];
    float t = 0.f;
#pragma unroll
    for (int i = 0; i < 16; i++) t += s[i];
    g_vmean[b*DMM + c] = t * (1.0f / Ll);
}

// ---------------- pre + measure: 2 warps per (b,l), 20 samples each ----------------
__global__ __launch_bounds__(256) void measure_kernel(const int* __restrict__ ridx) {
    __shared__ float smx[4][2][8], ssm[4][2][8];
    int tid = threadIdx.x, warp = tid >> 5, lane = tid & 31;
    int p = warp >> 1, half = warp & 1;
    int gp = blockIdx.x * 4 + p;           // 0..4095
    int l = gp & (Ll - 1), b = gp >> 11;
    const float4* qrow = (const float4*)&g_qp[((size_t)b*Ll + l) * DMM];
    float4 q0 = qrow[lane*4+0], q1 = qrow[lane*4+1], q2 = qrow[lane*4+2], q3 = qrow[lane*4+3];
    int idx = ridx[l*NUMK + half*20 + (lane >= 20 ? lane - 20 : lane)];
    float mx = -INFINITY, sm = 0.f;
#pragma unroll 4
    for (int j = 0; j < 20; j++) {
        int ki = __shfl_sync(0xffffffffu, idx, j);
        const float4* kr = (const float4*)&g_kp[((size_t)b*Ll + ki) * DMM];
        float4 k0 = kr[lane*4+0], k1 = kr[lane*4+1], k2 = kr[lane*4+2], k3 = kr[lane*4+3];
        float pv = q0.x*k0.x + q0.y*k0.y + q0.z*k0.z + q0.w*k0.w
                 + q1.x*k1.x + q1.y*k1.y + q1.z*k1.z + q1.w*k1.w
                 + q2.x*k2.x + q2.y*k2.y + q2.z*k2.z + q2.w*k2.w
                 + q3.x*k3.x + q3.y*k3.y + q3.z*k3.z + q3.w*k3.w;
        pv += __shfl_xor_sync(0xffffffffu, pv, 1);
        pv += __shfl_xor_sync(0xffffffffu, pv, 2);
        mx = fmaxf(mx, pv);
        sm += pv;
    }
    if ((lane & 3) == 0) {
        smx[p][half][lane >> 2] = mx;
        ssm[p][half][lane >> 2] = sm;
    }
    __syncthreads();
    if (tid < 32) {
        int pp = tid >> 3, h = tid & 7;
        float m = fmaxf(smx[pp][0][h], smx[pp][1][h]);
        float s = ssm[pp][0][h] + ssm[pp][1][h];
        int gpp = blockIdx.x * 4 + pp;
        int ll = gpp & (Ll - 1), bb = gpp >> 11;
        g_measure[((size_t)bb*Hh + h)*Ll + ll] = m - s * (1.0f / Ll);
    }
}

// ---------------- exact top-40 per (b,h): slot init + select + scatter (R12 proven) ----------------
__global__ __launch_bounds__(256) void topk_kernel() {
    int bh = blockIdx.x, t = threadIdx.x;
    for (int i = t; i < Ll; i += 256) g_slot[(size_t)bh*Ll + i] = -1;
    float v[8];
    const float* src = g_measure + (size_t)bh * Ll;
#pragma unroll
    for (int m = 0; m < 8; m++) v[m] = src[t + 256*m];
    __shared__ float swv[8];
    __shared__ int   swi[8];
    __shared__ int   s_best;
    __shared__ int   qsel[NUMQ];
    for (int s = 0; s < NUMQ; s++) {
        float bv = v[0]; int bi = t;
#pragma unroll
        for (int m = 1; m < 8; m++) {
            int i = t + 256*m;
            if (v[m] > bv || (v[m] == bv && i < bi)) { bv = v[m]; bi = i; }
        }
#pragma unroll
        for (int o = 16; o; o >>= 1) {
            float ov = __shfl_xor_sync(0xffffffffu, bv, o);
            int   oi = __shfl_xor_sync(0xffffffffu, bi, o);
            if (ov > bv || (ov == bv && oi < bi)) { bv = ov; bi = oi; }
        }
        if ((t & 31) == 0) { swv[t >> 5] = bv; swi[t >> 5] = bi; }
        __syncthreads();
        if (t == 0) {
            float rv = swv[0]; int ri = swi[0];
#pragma unroll
            for (int w = 1; w < 8; w++)
                if (swv[w] > rv || (swv[w] == rv && swi[w] < ri)) { rv = swv[w]; ri = swi[w]; }
            g_qidx[bh*NUMQ + s] = ri;
            qsel[s] = ri;
            s_best = ri;
        }
        __syncthreads();
        int ib = s_best;
        if ((ib & 255) == t) v[ib >> 8] = -INFINITY;
    }
    if (t < NUMQ) g_slot[(size_t)bh * Ll + qsel[t]] = t;
}

// ---------------- attention: 512 threads, block per (b,h,group-of-4-q) ----------------
__global__ __launch_bounds__(512) void attn_kernel(float* __restrict__ out_attn) {
    int blk = blockIdx.x;
    int g = blk % 10;
    int h = (blk / 10) % Hh;
    int b = blk / (10 * Hh);
    __shared__ float qs[4][Dd];
    __shared__ float sc[4][Ll];
    __shared__ float red[16];
    __shared__ float pvs[8][4][Dd];
    __shared__ int qix[4];
    int tid = threadIdx.x;
    int lane = tid & 31, w = tid >> 5;      // 16 warps
    if (tid < 4) qix[tid] = g_qidx[(b*Hh + h)*NUMQ + g*4 + tid];
    __syncthreads();
    if (tid < 256) {
        int qq = tid >> 6, d = tid & 63;
        qs[qq][d] = g_qp[((size_t)b*Ll + qix[qq])*DMM + h*Dd + d];
    }
    __syncthreads();
    const float scale = 0.125f;

    int quarter = lane & 3, keyoff = lane >> 2;
    float4 qr[4][4];
#pragma unroll
    for (int q = 0; q < 4; q++)
#pragma unroll
        for (int c = 0; c < 4; c++)
            qr[q][c] = *(float4*)&qs[q][quarter*16 + c*4];

    for (int pass = 0; pass < 16; pass++) {
        int j = w*128 + pass*8 + keyoff;
        const float4* kr = (const float4*)&g_kp[((size_t)b*Ll + j)*DMM + h*Dd + quarter*16];
        float4 k0 = kr[0], k1 = kr[1], k2 = kr[2], k3 = kr[3];
        float p[4];
#pragma unroll
        for (int q = 0; q < 4; q++) {
            p[q] = qr[q][0].x*k0.x + qr[q][0].y*k0.y + qr[q][0].z*k0.z + qr[q][0].w*k0.w
                 + qr[q][1].x*k1.x + qr[q][1].y*k1.y + qr[q][1].z*k1.z + qr[q][1].w*k1.w
                 + qr[q][2].x*k2.x + qr[q][2].y*k2.y + qr[q][2].z*k2.z + qr[q][2].w*k2.w
                 + qr[q][3].x*k3.x + qr[q][3].y*k3.y + qr[q][3].z*k3.z + qr[q][3].w*k3.w;
            p[q] += __shfl_xor_sync(0xffffffffu, p[q], 1);
            p[q] += __shfl_xor_sync(0xffffffffu, p[q], 2);
        }
        if (quarter == 0) {
            sc[0][j] = p[0] * scale; sc[1][j] = p[1] * scale;
            sc[2][j] = p[2] * scale; sc[3][j] = p[3] * scale;
        }
    }
    __syncthreads();
#pragma unroll
    for (int q = 0; q < 4; q++) {
        float m = -INFINITY;
        for (int j = tid; j < Ll; j += 512) m = fmaxf(m, sc[q][j]);
#pragma unroll
        for (int o = 16; o; o >>= 1) m = fmaxf(m, __shfl_xor_sync(0xffffffffu, m, o));
        if (lane == 0) red[w] = m;
        __syncthreads();
        m = red[0];
#pragma unroll
        for (int i = 1; i < 16; i++) m = fmaxf(m, red[i]);
        __syncthreads();
        float s = 0.f;
        for (int j = tid; j < Ll; j += 512) { float e = expf(sc[q][j] - m); sc[q][j] = e; s += e; }
#pragma unroll
        for (int o = 16; o; o >>= 1) s += __shfl_xor_sync(0xffffffffu, s, o);
        if (lane == 0) red[w] = s;
        __syncthreads();
        float tot = red[0];
#pragma unroll
        for (int i = 1; i < 16; i++) tot += red[i];
        float inv = 1.0f / tot;
        size_t aoff = ((size_t)(b*Hh + h)*NUMQ + g*4 + q) * Ll;
        for (int j = tid; j < Ll; j += 512) {
            float p = sc[q][j] * inv;
            sc[q][j] = p;
            out_attn[aoff + j] = p;
        }
        __syncthreads();
    }
    int d = tid & 63, part = tid >> 6;
    float a0 = 0.f, a1 = 0.f, a2 = 0.f, a3 = 0.f;
    int j0 = part * 256;
    const float* vbase = &g_vp[((size_t)b*Ll + j0)*DMM + h*Dd + d];
    for (int jb = 0; jb < 256; jb++) {
        float vv = vbase[(size_t)jb*DMM];
        int j = j0 + jb;
        a0 += sc[0][j]*vv; a1 += sc[1][j]*vv; a2 += sc[2][j]*vv; a3 += sc[3][j]*vv;
    }
    pvs[part][0][d] = a0; pvs[part][1][d] = a1;
    pvs[part][2][d] = a2; pvs[part][3][d] = a3;
    __syncthreads();
    if (part == 0) {
#pragma unroll
        for (int q = 0; q < 4; q++) {
            float r = 0.f;
#pragma unroll
            for (int pp = 0; pp < 8; pp++) r += pvs[pp][q][d];
            g_outsel[((size_t)((b*Hh + h)*NUMQ) + g*4 + q)*Dd + d] = r;
        }
    }
}

// ---------------- residual + layernorm (vmean/outsel compose) ----------------
__global__ __launch_bounds__(256) void ln_kernel(const float* __restrict__ qin,
                                                 const float* __restrict__ gamma,
                                                 const float* __restrict__ beta,
                                                 float* __restrict__ out)
{
    int row = blockIdx.x;            // Bb*Ll
    int b = row >> 11, l = row & (Ll - 1);
    int tid = threadIdx.x;
    __shared__ float sm[8], sm2[8];
    __shared__ int slots[8];
    if (tid < 8) slots[tid] = g_slot[(size_t)(b*Hh + tid)*Ll + l];
    __syncthreads();
    const float* qr = qin + (size_t)row * DMM;
    int c0 = tid, c1 = tid + 256;
    int h0 = c0 >> 6, h1 = c1 >> 6;
    int s0i = slots[h0], s1i = slots[h1];
    float ctx0 = (s0i >= 0)
        ? g_outsel[((size_t)((b*Hh + h0)*NUMQ) + s0i)*Dd + (c0 & 63)]
        : g_vmean[b*DMM + c0];
    float ctx1 = (s1i >= 0)
        ? g_outsel[((size_t)((b*Hh + h1)*NUMQ) + s1i)*Dd + (c1 & 63)]
        : g_vmean[b*DMM + c1];
    float v0 = ctx0 + qr[c0];
    float v1 = ctx1 + qr[c1];
    int lane = tid & 31, w = tid >> 5;
    float s = v0 + v1;
#pragma unroll
    for (int o = 16; o; o >>= 1) s += __shfl_xor_sync(0xffffffffu, s, o);
    if (lane == 0) sm[w] = s;
    __syncthreads();
    float mean = (sm[0]+sm[1]+sm[2]+sm[3]+sm[4]+sm[5]+sm[6]+sm[7]) * (1.0f / DMM);
    float d0 = v0 - mean, d1 = v1 - mean;
    float s2 = d0*d0 + d1*d1;
#pragma unroll
    for (int o = 16; o; o >>= 1) s2 += __shfl_xor_sync(0xffffffffu, s2, o);
    if (lane == 0) sm2[w] = s2;
    __syncthreads();
    float var = (sm2[0]+sm2[1]+sm2[2]+sm2[3]+sm2[4]+sm2[5]+sm2[6]+sm2[7]) * (1.0f / DMM);
    float invstd = rsqrtf(var + LN_EPS);
    out[(size_t)row*DMM + c0] = d0 * invstd * gamma[c0] + beta[c0];
    out[(size_t)row*DMM + c1] = d1 * invstd * gamma[c1] + beta[c1];
}

// ---------------- launch ----------------
extern "C" void kernel_launch(void* const* d_in, const int* in_sizes, int n_in,
                              void* d_out, int out_size)
{
    const float* q     = (const float*)d_in[0];
    const float* k     = (const float*)d_in[1];
    const float* v     = (const float*)d_in[2];
    const float* Wq    = (const float*)d_in[3];
    const float* bq    = (const float*)d_in[4];
    const float* Wk    = (const float*)d_in[5];
    const float* bk    = (const float*)d_in[6];
    const float* Wv    = (const float*)d_in[7];
    const float* bv    = (const float*)d_in[8];
    const float* gamma = (const float*)d_in[9];
    const float* beta  = (const float*)d_in[10];
    const int*   ridx  = (const int*)d_in[11];
    float* out      = (float*)d_out;
    float* out_attn = out + (size_t)Bb * Ll * DMM;

    static bool init_done = false;
    static cudaStream_t s1;
    static cudaEvent_t evQK, evV;
    if (!init_done) {
        cudaFuncSetAttribute(gemm_tc_kernel,
                             cudaFuncAttributeMaxDynamicSharedMemorySize, GEMM_SMEM);
        cudaStreamCreateWithFlags(&s1, cudaStreamNonBlocking);
        cudaEventCreateWithFlags(&evQK, cudaEventDisableTiming);
        cudaEventCreateWithFlags(&evV, cudaEventDisableTiming);
        init_done = true;
    }

    // stream0: wsplit -> gemm(q,k) -> measure -> topk -> [wait v-chain] -> attn -> ln
    // stream1:            [after gemm_qk] gemm(v) -> vmean -> evV
    wsplit_t_kernel<<<dim3(16, 16, 3), dim3(32, 8)>>>(Wq, Wk, Wv);
    gemm_tc_kernel<<<dim3(4, 32, 2), 512, GEMM_SMEM>>>(q, k, v, bq, bk, bv, 0);
    cudaEventRecord(evQK, 0);

    cudaStreamWaitEvent(s1, evQK, 0);
    gemm_tc_kernel<<<dim3(4, 32, 1), 512, GEMM_SMEM, s1>>>(q, k, v, bq, bk, bv, 2);
    vmean_part_kernel<<<256, DMM, 0, s1>>>();
    vmean_reduce_kernel<<<Bb, DMM, 0, s1>>>();
    cudaEventRecord(evV, s1);

    measure_kernel<<<Bb * Ll / 4, 256>>>(ridx);
    topk_kernel<<<Bb * Hh, 256>>>();

    cudaStreamWaitEvent(0, evV, 0);
    attn_kernel<<<Bb * Hh * 10, 512>>>(out_attn);
    ln_kernel<<<Bb * Ll, 256>>>(q, gamma, beta, out);
}